// round 1
// baseline (speedup 1.0000x reference)
#include <cuda_runtime.h>
#include <math_constants.h>

#define NN      8000
#define NPAD    8192
#define NCLS    20
#define NBOX    400
#define IMGW    1333.0f
#define IMGH    800.0f
#define TOPK    100
#define MAXM    400

// ---------------- device scratch (no allocations allowed) ----------------
__device__ float               g_fg[NPAD];     // fg score per transposed index j
__device__ float4              g_box[NPAD];    // clipped box per j
__device__ unsigned char       g_valid[NPAD];  // finite && fg>0.05
__device__ unsigned long long  g_keys[NPAD];   // sorted: (desc-score | j)
__device__ unsigned char       g_keep[NPAD];   // keep flag per SORTED position
__device__ unsigned int        g_maxBits;      // float bits of max clipped coord (>=0)

// descending-sortable mapping of a float (ascending u32 sort -> descending float)
__device__ __forceinline__ unsigned int ord_desc(float f) {
    unsigned int u = __float_as_uint(f);
    unsigned int m = (u & 0x80000000u) ? ~u : (u | 0x80000000u); // ascending-sortable
    return ~m;                                                   // descending
}

__global__ void k_init() { g_maxBits = 0u; }

// ---------------- prep: transpose-gather, clip, keys ----------------
__global__ void k_prep(const float* __restrict__ boxes, const float* __restrict__ scores) {
    int j = blockIdx.x * blockDim.x + threadIdx.x;   // transposed index, grid == NPAD
    float localmax = 0.0f;
    if (j < NN) {
        int c = j % NCLS;
        int b = j / NCLS;
        int i = c * NBOX + b;                        // original index
        float x1 = boxes[i * 4 + 0];
        float y1 = boxes[i * 4 + 1];
        float x2 = boxes[i * 4 + 2];
        float y2 = boxes[i * 4 + 3];
        float s0 = scores[i * 2 + 0];
        float s1 = scores[i * 2 + 1];
        bool fin = isfinite(x1) && isfinite(y1) && isfinite(x2) && isfinite(y2)
                && isfinite(s0) && isfinite(s1);
        x1 = fminf(fmaxf(x1, 0.0f), IMGW);
        x2 = fminf(fmaxf(x2, 0.0f), IMGW);
        y1 = fminf(fmaxf(y1, 0.0f), IMGH);
        y2 = fminf(fmaxf(y2, 0.0f), IMGH);
        bool valid = fin && (s0 > 0.05f);
        float masked = valid ? s0 : -CUDART_INF_F;
        g_fg[j]    = s0;
        g_box[j]   = make_float4(x1, y1, x2, y2);
        g_valid[j] = valid ? 1 : 0;
        g_keys[j]  = ((unsigned long long)ord_desc(masked) << 32) | (unsigned int)j;
        localmax = fmaxf(fmaxf(x1, x2), fmaxf(y1, y2));
    } else {
        g_fg[j]    = 0.0f;
        g_box[j]   = make_float4(0.f, 0.f, 0.f, 0.f);
        g_valid[j] = 0;
        g_keys[j]  = 0xFFFFFFFFFFFFFFFFull;          // padding sorts last
    }
    g_keep[j] = 0;
    // warp-level max, one atomic per warp (coords are >= 0, so uint-bit max == float max)
    unsigned int wb = __reduce_max_sync(0xFFFFFFFFu, __float_as_uint(localmax));
    if ((threadIdx.x & 31) == 0) atomicMax(&g_maxBits, wb);
}

// ---------------- sort: single-block bitonic on 8192 u64 keys ----------------
__global__ void k_sort() {
    extern __shared__ unsigned long long s[];
    const int tid = threadIdx.x;                      // 1024 threads
    for (int t = tid; t < NPAD; t += 1024) s[t] = g_keys[t];
    __syncthreads();
    for (int k = 2; k <= NPAD; k <<= 1) {
        for (int jj = k >> 1; jj > 0; jj >>= 1) {
            for (int t = tid; t < NPAD; t += 1024) {
                int ixj = t ^ jj;
                if (ixj > t) {
                    unsigned long long a = s[t];
                    unsigned long long b = s[ixj];
                    bool asc = ((t & k) == 0);
                    if ((a > b) == asc) { s[t] = b; s[ixj] = a; }
                }
            }
            __syncthreads();
        }
    }
    for (int t = tid; t < NPAD; t += 1024) g_keys[t] = s[t];
}

// ---------------- NMS: one block per class, exact replication of reference IoU ----------------
__global__ void k_nms() {
    __shared__ float4         sb[MAXM];      // class-offset-shifted boxes, sorted order
    __shared__ unsigned short st[MAXM];      // sorted position of each entry
    __shared__ unsigned char  sk[MAXM];      // keep flags
    __shared__ int            s_base;
    __shared__ int            warp_cnt[16];  // 512 threads = 16 warps

    const int cls = blockIdx.x;
    const int tid = threadIdx.x;
    const int lane = tid & 31;
    const int wid  = tid >> 5;

    const float offv  = __fadd_rn(__uint_as_float(g_maxBits), 1.0f);   // max + 1.0
    const float shift = __fmul_rn((float)cls, offv);                   // cls * offset

    if (tid == 0) s_base = 0;
    __syncthreads();

    // ordered compaction of this class's VALID entries from the globally sorted list
    for (int r = 0; r < NPAD; r += blockDim.x) {
        int t = r + tid;
        unsigned long long key = g_keys[t];
        unsigned int jv = (unsigned int)key;
        bool pred = (jv < NN) && g_valid[jv] && ((jv % NCLS) == (unsigned)cls);
        unsigned int mask = __ballot_sync(0xFFFFFFFFu, pred);
        if (lane == 0) warp_cnt[wid] = __popc(mask);
        __syncthreads();
        int wbase = 0;
        #pragma unroll
        for (int w = 0; w < 16; w++) if (w < wid) wbase += warp_cnt[w];
        int pos = s_base + wbase + __popc(mask & ((1u << lane) - 1u));
        if (pred) {
            float4 bx = g_box[jv];
            sb[pos] = make_float4(__fadd_rn(bx.x, shift), __fadd_rn(bx.y, shift),
                                  __fadd_rn(bx.z, shift), __fadd_rn(bx.w, shift));
            st[pos] = (unsigned short)t;
            sk[pos] = 1;
        }
        __syncthreads();
        if (tid == 0) {
            int tot = 0;
            #pragma unroll
            for (int w = 0; w < 16; w++) tot += warp_cnt[w];
            s_base += tot;
        }
        __syncthreads();
    }
    const int m = s_base;   // <= 400

    // greedy NMS, sequential over i, parallel suppression over j>i
    for (int i = 0; i < m; i++) {
        __syncthreads();
        if (!sk[i]) continue;                 // uniform branch
        float4 bi = sb[i];
        float ai = __fmul_rn(__fsub_rn(bi.z, bi.x), __fsub_rn(bi.w, bi.y));
        for (int t = i + 1 + tid; t < m; t += blockDim.x) {
            if (!sk[t]) continue;
            float4 bj = sb[t];
            float iw = fmaxf(__fsub_rn(fminf(bi.z, bj.z), fmaxf(bi.x, bj.x)), 0.0f);
            float ih = fmaxf(__fsub_rn(fminf(bi.w, bj.w), fmaxf(bi.y, bj.y)), 0.0f);
            float inter = __fmul_rn(iw, ih);
            float aj = __fmul_rn(__fsub_rn(bj.z, bj.x), __fsub_rn(bj.w, bj.y));
            float uni = __fsub_rn(__fadd_rn(ai, aj), inter);
            float iou = (uni > 0.0f) ? __fdiv_rn(inter, uni) : 0.0f;
            if (iou > 0.5f) sk[t] = 0;
        }
    }
    __syncthreads();
    for (int t = tid; t < m; t += blockDim.x) g_keep[st[t]] = sk[t];
}

// ---------------- output: first TOPK kept entries in global sorted order ----------------
__global__ void k_out(float* __restrict__ out) {
    __shared__ int psum[1024];
    const int tid = threadIdx.x;             // 1024 threads

    // default-initialize all 700 outputs
    if (tid < 4 * TOPK) out[tid] = 0.0f;                 // boxes
    if (tid < TOPK) {
        out[4 * TOPK + tid]     = 0.0f;                  // scores
        out[5 * TOPK + tid]     = -1.0f;                 // cls
        out[6 * TOPK + tid]     = 0.0f;                  // valid
    }

    // local keep flags + block prefix scan (8 per thread, contiguous chunks)
    const int base_idx = tid * 8;
    unsigned char lk[8];
    int cnt = 0;
    #pragma unroll
    for (int q = 0; q < 8; q++) { lk[q] = g_keep[base_idx + q]; cnt += lk[q]; }
    psum[tid] = cnt;
    __syncthreads();
    for (int d = 1; d < 1024; d <<= 1) {
        int v = (tid >= d) ? psum[tid - d] : 0;
        __syncthreads();
        psum[tid] += v;
        __syncthreads();
    }
    int rank = psum[tid] - cnt;              // exclusive prefix

    #pragma unroll
    for (int q = 0; q < 8; q++) {
        if (lk[q] && rank < TOPK) {
            int t = base_idx + q;
            unsigned int jv = (unsigned int)g_keys[t];
            float4 bx = g_box[jv];
            out[rank * 4 + 0] = bx.x;
            out[rank * 4 + 1] = bx.y;
            out[rank * 4 + 2] = bx.z;
            out[rank * 4 + 3] = bx.w;
            out[4 * TOPK + rank] = g_fg[jv];
            out[5 * TOPK + rank] = (float)(jv % NCLS);
            out[6 * TOPK + rank] = 1.0f;
        }
        rank += lk[q];
    }
}

// ---------------- launch ----------------
extern "C" void kernel_launch(void* const* d_in, const int* in_sizes, int n_in,
                              void* d_out, int out_size) {
    // inputs per setup_inputs order: pred_cls (int32, N), boxes (f32, N*4), scores (f32, N*2)
    const float* boxes  = (const float*)d_in[1];
    const float* scores = (const float*)d_in[2];
    float* out = (float*)d_out;

    cudaFuncSetAttribute(k_sort, cudaFuncAttributeMaxDynamicSharedMemorySize, NPAD * 8);

    k_init<<<1, 1>>>();
    k_prep<<<NPAD / 256, 256>>>(boxes, scores);
    k_sort<<<1, 1024, NPAD * 8>>>();
    k_nms<<<NCLS, 512>>>();
    k_out<<<1, 1024>>>(out);
}

// round 2
// speedup vs baseline: 1.2100x; 1.2100x over previous
#include <cuda_runtime.h>
#include <math_constants.h>

#define NN     8000
#define NCLS   20
#define NBOX   400
#define SORTN  512
#define IMGW   1333.0f
#define IMGH   800.0f
#define TOPK   100
#define NSEL   (NCLS * TOPK)      // 2000
#define SORT2  2048
#define NW     13                 // 400 bits -> 13 u32 words
#define SENTK  0xFFFFFFFFFFFFFFFFull
#define FULLM  0xFFFFFFFFu

// ---------------- device scratch ----------------
__device__ unsigned long long g_ckey[NN];    // key per ORIGINAL index i=c*400+b
__device__ float4             g_cbox[NN];    // clipped unshifted box per i
__device__ unsigned int       g_blockMax[32];
__device__ unsigned long long g_selkey[NSEL];// per class: top-100 kept keys, sentinel-padded

// descending-sortable mapping (ascending u32 sort -> descending float)
__device__ __forceinline__ unsigned int ord_desc(float f) {
    unsigned int u = __float_as_uint(f);
    unsigned int m = (u & 0x80000000u) ? ~u : (u | 0x80000000u);
    return ~m;
}
__device__ __forceinline__ float inv_ord(unsigned int o) {
    unsigned int m = ~o;
    unsigned int u = (m & 0x80000000u) ? (m & 0x7FFFFFFFu) : ~m;
    return __uint_as_float(u);
}

// ---------------- prep: transpose-gather, clip, keys, block max ----------------
__global__ void k_prep(const float* __restrict__ boxes, const float* __restrict__ scores) {
    int j = blockIdx.x * blockDim.x + threadIdx.x;   // transposed index
    float localmax = 0.0f;
    if (j < NN) {
        int c = j % NCLS;
        int b = j / NCLS;
        int i = c * NBOX + b;                        // original index
        float x1 = boxes[i * 4 + 0];
        float y1 = boxes[i * 4 + 1];
        float x2 = boxes[i * 4 + 2];
        float y2 = boxes[i * 4 + 3];
        float s0 = scores[i * 2 + 0];
        float s1 = scores[i * 2 + 1];
        bool fin = isfinite(x1) && isfinite(y1) && isfinite(x2) && isfinite(y2)
                && isfinite(s0) && isfinite(s1);
        x1 = fminf(fmaxf(x1, 0.0f), IMGW);
        x2 = fminf(fmaxf(x2, 0.0f), IMGW);
        y1 = fminf(fmaxf(y1, 0.0f), IMGH);
        y2 = fminf(fmaxf(y2, 0.0f), IMGH);
        bool valid = fin && (s0 > 0.05f);
        float masked = valid ? s0 : -CUDART_INF_F;
        g_ckey[i] = ((unsigned long long)ord_desc(masked) << 32) | (unsigned int)j;
        g_cbox[i] = make_float4(x1, y1, x2, y2);
        localmax = fmaxf(fmaxf(x1, x2), fmaxf(y1, y2));
    }
    __shared__ unsigned int wmax[8];
    unsigned int wb = __reduce_max_sync(FULLM, __float_as_uint(localmax));
    if ((threadIdx.x & 31) == 0) wmax[threadIdx.x >> 5] = wb;
    __syncthreads();
    if (threadIdx.x == 0) {
        unsigned int mx = 0;
        #pragma unroll
        for (int w = 0; w < 8; w++) mx = max(mx, wmax[w]);
        g_blockMax[blockIdx.x] = mx;
    }
}

// ---------------- per-class: sort 512 keys, mask-matrix NMS, emit top-100 kept ----------------
__global__ void __launch_bounds__(256) k_cls() {
    __shared__ unsigned long long skey[SORTN];   // 4 KB
    __shared__ float4             sbox[NBOX];    // 6.4 KB (shifted)
    __shared__ unsigned int       smask[NBOX * NW]; // 20.8 KB
    __shared__ float              s_shift;

    const int cls  = blockIdx.x;
    const int tid  = threadIdx.x;                // 256
    const int lane = tid & 31;

    // global coord max -> shift (matches reference op order)
    if (tid < 32) {
        unsigned int v = g_blockMax[tid];
        v = __reduce_max_sync(FULLM, v);
        if (tid == 0) {
            float offv = __fadd_rn(__uint_as_float(v), 1.0f);
            s_shift = __fmul_rn((float)cls, offv);
        }
    }

    // load this class's 400 keys (+ sentinel padding), count valid
    int t0 = tid, t1 = tid + 256;
    unsigned long long k0 = (t0 < NBOX) ? g_ckey[cls * NBOX + t0] : SENTK;
    unsigned long long k1 = (t1 < NBOX) ? g_ckey[cls * NBOX + t1] : SENTK;
    skey[t0] = k0;
    skey[t1] = k1;
    bool v0 = (t0 < NBOX) && ((unsigned int)(k0 >> 32) != 0xFF800000u);
    bool v1 = (t1 < NBOX) && ((unsigned int)(k1 >> 32) != 0xFF800000u);
    int m = __syncthreads_count(v0) + __syncthreads_count(v1);   // also a barrier

    // bitonic sort 512 ascending (valid entries first, by score desc / idx asc)
    for (int k = 2; k <= SORTN; k <<= 1) {
        for (int jj = k >> 1; jj > 0; jj >>= 1) {
            #pragma unroll
            for (int t = tid; t < SORTN; t += 256) {
                int ixj = t ^ jj;
                if (ixj > t) {
                    unsigned long long a = skey[t];
                    unsigned long long b = skey[ixj];
                    bool asc = ((t & k) == 0);
                    if ((a > b) == asc) { skey[t] = b; skey[ixj] = a; }
                }
            }
            __syncthreads();
        }
    }

    // gather shifted boxes in sorted order
    float shift = s_shift;
    for (int t = tid; t < m; t += 256) {
        unsigned int j = (unsigned int)skey[t];
        int b = j / NCLS;
        float4 bx = g_cbox[cls * NBOX + b];
        sbox[t] = make_float4(__fadd_rn(bx.x, shift), __fadd_rn(bx.y, shift),
                              __fadd_rn(bx.z, shift), __fadd_rn(bx.w, shift));
    }
    __syncthreads();

    // suppression mask matrix: smask[i][w] bit b set  <=>  iou(i, 32w+b) > 0.5 and 32w+b > i
    int total = m * NW;
    for (int lin = tid; lin < total; lin += 256) {
        int i = lin / NW;
        int w = lin - i * NW;
        unsigned int bits = 0;
        int lo = w * 32;
        int hi = min(m, lo + 32);
        int st = max(lo, i + 1);
        if (st < hi) {
            float4 bi = sbox[i];
            float ai = __fmul_rn(__fsub_rn(bi.z, bi.x), __fsub_rn(bi.w, bi.y));
            for (int jd = st; jd < hi; jd++) {
                float4 bj = sbox[jd];
                float iw = fmaxf(__fsub_rn(fminf(bi.z, bj.z), fmaxf(bi.x, bj.x)), 0.0f);
                float ih = fmaxf(__fsub_rn(fminf(bi.w, bj.w), fmaxf(bi.y, bj.y)), 0.0f);
                float inter = __fmul_rn(iw, ih);
                float aj = __fmul_rn(__fsub_rn(bj.z, bj.x), __fsub_rn(bj.w, bj.y));
                float uni = __fsub_rn(__fadd_rn(ai, aj), inter);
                float iou = (uni > 0.0f) ? __fdiv_rn(inter, uni) : 0.0f;
                if (iou > 0.5f) bits |= 1u << (jd - lo);
            }
        }
        smask[i * NW + w] = bits;
    }
    __syncthreads();

    // sequential greedy scan (warp 0 only, warp-synchronous, no block barriers)
    if (tid < 32) {
        unsigned int mysup = 0;                      // lane w owns suppressed bits [32w,32w+32)
        for (int i = 0; i < m; i++) {
            unsigned int supw = __shfl_sync(FULLM, mysup, i >> 5);
            if (!((supw >> (i & 31)) & 1u)) {
                if (lane < NW) mysup |= smask[i * NW + lane];
            }
        }
        // ordered compaction of kept entries, first TOPK only
        int cnt = 0;
        for (int base = 0; base < m; base += 32) {
            int t = base + lane;
            unsigned int supw = __shfl_sync(FULLM, mysup, t >> 5);
            bool kept = (t < m) && !((supw >> (t & 31)) & 1u);
            unsigned int bal = __ballot_sync(FULLM, kept);
            int pos = cnt + __popc(bal & ((1u << lane) - 1u));
            if (kept && pos < TOPK) g_selkey[cls * TOPK + pos] = skey[t];
            cnt += __popc(bal);
        }
        if (cnt > TOPK) cnt = TOPK;
        for (int p = cnt + lane; p < TOPK; p += 32) g_selkey[cls * TOPK + p] = SENTK;
    }
}

// ---------------- final: sort 2048 candidate keys, write top-100 records ----------------
__global__ void __launch_bounds__(512) k_final(const int* __restrict__ pred_cls,
                                               float* __restrict__ out) {
    __shared__ unsigned long long sk[SORT2];     // 16 KB
    const int tid = threadIdx.x;                 // 512

    for (int t = tid; t < SORT2; t += 512) sk[t] = (t < NSEL) ? g_selkey[t] : SENTK;
    __syncthreads();

    for (int k = 2; k <= SORT2; k <<= 1) {
        for (int jj = k >> 1; jj > 0; jj >>= 1) {
            #pragma unroll
            for (int t = tid; t < SORT2; t += 512) {
                int ixj = t ^ jj;
                if (ixj > t) {
                    unsigned long long a = sk[t];
                    unsigned long long b = sk[ixj];
                    bool asc = ((t & k) == 0);
                    if ((a > b) == asc) { sk[t] = b; sk[ixj] = a; }
                }
            }
            __syncthreads();
        }
    }

    if (tid < TOPK) {
        unsigned long long key = sk[tid];
        if (key != SENTK) {
            unsigned int j = (unsigned int)key;
            int c = j % NCLS;
            int b = j / NCLS;
            int idx = c * NBOX + b;
            float4 bx = g_cbox[idx];
            out[tid * 4 + 0] = bx.x;
            out[tid * 4 + 1] = bx.y;
            out[tid * 4 + 2] = bx.z;
            out[tid * 4 + 3] = bx.w;
            out[4 * TOPK + tid] = inv_ord((unsigned int)(key >> 32));
            out[5 * TOPK + tid] = (float)pred_cls[idx];
            out[6 * TOPK + tid] = 1.0f;
        } else {
            out[tid * 4 + 0] = 0.0f;
            out[tid * 4 + 1] = 0.0f;
            out[tid * 4 + 2] = 0.0f;
            out[tid * 4 + 3] = 0.0f;
            out[4 * TOPK + tid] = 0.0f;
            out[5 * TOPK + tid] = -1.0f;
            out[6 * TOPK + tid] = 0.0f;
        }
    }
}

// ---------------- launch ----------------
extern "C" void kernel_launch(void* const* d_in, const int* in_sizes, int n_in,
                              void* d_out, int out_size) {
    const int*   pred_cls = (const int*)d_in[0];
    const float* boxes    = (const float*)d_in[1];
    const float* scores   = (const float*)d_in[2];
    float* out = (float*)d_out;

    k_prep<<<32, 256>>>(boxes, scores);
    k_cls<<<NCLS, 256>>>();
    k_final<<<1, 512>>>(pred_cls, out);
}

// round 3
// speedup vs baseline: 1.8242x; 1.5076x over previous
#include <cuda_runtime.h>
#include <math_constants.h>

#define NN     8000
#define NCLS   20
#define NBOX   400
#define SORTN  512
#define IMGW   1333.0f
#define IMGH   800.0f
#define TOPK   100
#define NSEL   (NCLS * TOPK)     // 2000
#define SORT2  2048
#define NW     13                // 400 bits -> 13 u32 words
#define SENTK  0xFFFFFFFFFFFFFFFFull
#define FULLM  0xFFFFFFFFu
#define NTHR   512

// ---------------- device scratch (statically zero-initialized; reset by last block) ----
__device__ unsigned long long g_selkey[NSEL];
__device__ unsigned int       g_maxBits = 0u;
__device__ unsigned int       g_cnt1   = 0u;
__device__ unsigned int       g_done   = 0u;

// descending-sortable mapping (ascending u64 sort -> descending float score)
__device__ __forceinline__ unsigned int ord_desc(float f) {
    unsigned int u = __float_as_uint(f);
    unsigned int m = (u & 0x80000000u) ? ~u : (u | 0x80000000u);
    return ~m;
}
__device__ __forceinline__ float inv_ord(unsigned int o) {
    unsigned int m = ~o;
    unsigned int u = (m & 0x80000000u) ? (m & 0x7FFFFFFFu) : ~m;
    return __uint_as_float(u);
}

__global__ void __launch_bounds__(NTHR, 1)
k_all(const float* __restrict__ boxes, const float* __restrict__ scores,
      const int* __restrict__ pred_cls, float* __restrict__ out)
{
    __shared__ __align__(16) unsigned long long skey[SORTN];   // 4 KB
    __shared__ __align__(16) float4       s_cbox[NBOX];        // 6.4 KB (clipped, by box idx b)
    __shared__ __align__(16) float4       s_sbox[NBOX];        // 6.4 KB (shifted, sorted order)
    __shared__ __align__(16) unsigned int s_mask[NBOX * NW];   // 20.8 KB; reused for final sort
    __shared__ unsigned int s_wmax[16];
    __shared__ float        s_shift;
    __shared__ int          s_last;

    const int cls  = blockIdx.x;
    const int tid  = threadIdx.x;
    const int lane = tid & 31;

    // ---------- phase A: load own class, clip, keys, local max ----------
    float lmax = 0.0f;
    bool  valid = false;
    unsigned long long key = SENTK;
    if (tid < NBOX) {
        float4 bx = reinterpret_cast<const float4*>(boxes)[cls * NBOX + tid];
        float2 sc = reinterpret_cast<const float2*>(scores)[cls * NBOX + tid];
        bool fin = isfinite(bx.x) && isfinite(bx.y) && isfinite(bx.z) && isfinite(bx.w)
                && isfinite(sc.x) && isfinite(sc.y);
        float x1 = fminf(fmaxf(bx.x, 0.0f), IMGW);
        float y1 = fminf(fmaxf(bx.y, 0.0f), IMGH);
        float x2 = fminf(fmaxf(bx.z, 0.0f), IMGW);
        float y2 = fminf(fmaxf(bx.w, 0.0f), IMGH);
        valid = fin && (sc.x > 0.05f);
        float masked = valid ? sc.x : -CUDART_INF_F;
        unsigned int j = (unsigned int)(tid * NCLS + cls);       // transposed index
        key = ((unsigned long long)ord_desc(masked) << 32) | j;
        s_cbox[tid] = make_float4(x1, y1, x2, y2);
        lmax = fmaxf(fmaxf(x1, x2), fmaxf(y1, y2));
    }
    skey[tid] = key;
    unsigned int wb = __reduce_max_sync(FULLM, __float_as_uint(lmax));
    if (lane == 0) s_wmax[tid >> 5] = wb;
    const int m = __syncthreads_count(valid);                    // barrier: skey/cbox/wmax ready

    // publish block max, arrive at grid rendezvous (hidden behind the sort below)
    if (tid == 0) {
        unsigned int mx = 0;
        #pragma unroll
        for (int w = 0; w < 16; w++) mx = max(mx, s_wmax[w]);
        atomicMax(&g_maxBits, mx);
        __threadfence();
        atomicAdd(&g_cnt1, 1u);
    }

    // ---------- phase B: bitonic sort 512 keys (1 elem/thread) ----------
    for (int k = 2; k <= SORTN; k <<= 1) {
        for (int jj = k >> 1; jj > 0; jj >>= 1) {
            int ixj = tid ^ jj;
            if (ixj > tid) {
                unsigned long long a = skey[tid];
                unsigned long long b = skey[ixj];
                bool asc = ((tid & k) == 0);
                if ((a > b) == asc) { skey[tid] = b; skey[ixj] = a; }
            }
            __syncthreads();
        }
    }

    // ---------- phase C: wait for all 20 block maxes, compute shift ----------
    if (tid == 0) {
        volatile unsigned int* vc = &g_cnt1;
        while (*vc < (unsigned)NCLS) { }
        __threadfence();
        unsigned int mv = atomicMax(&g_maxBits, 0u);             // atomic read
        float offv = __fadd_rn(__uint_as_float(mv), 1.0f);       // max + 1.0
        s_shift = __fmul_rn((float)cls, offv);                   // cls * offset
    }
    __syncthreads();

    // ---------- phase D: shifted boxes in sorted order ----------
    const float shift = s_shift;
    if (tid < m) {
        unsigned int j = (unsigned int)skey[tid];
        int b = (int)(j / NCLS);
        float4 bx = s_cbox[b];
        s_sbox[tid] = make_float4(__fadd_rn(bx.x, shift), __fadd_rn(bx.y, shift),
                                  __fadd_rn(bx.z, shift), __fadd_rn(bx.w, shift));
    }
    __syncthreads();

    // ---------- phase E: suppression mask matrix (iou>0.5 && j>i) ----------
    const int total = m * NW;
    for (int lin = tid; lin < total; lin += NTHR) {
        int i = lin / NW;
        int w = lin - i * NW;
        unsigned int bits = 0;
        int lo = w * 32;
        int hi = min(m, lo + 32);
        int st = max(lo, i + 1);
        if (st < hi) {
            float4 bi = s_sbox[i];
            float ai = __fmul_rn(__fsub_rn(bi.z, bi.x), __fsub_rn(bi.w, bi.y));
            for (int jd = st; jd < hi; jd++) {
                float4 bj = s_sbox[jd];
                float iw = fmaxf(__fsub_rn(fminf(bi.z, bj.z), fmaxf(bi.x, bj.x)), 0.0f);
                float ih = fmaxf(__fsub_rn(fminf(bi.w, bj.w), fmaxf(bi.y, bj.y)), 0.0f);
                float inter = __fmul_rn(iw, ih);
                float aj = __fmul_rn(__fsub_rn(bj.z, bj.x), __fsub_rn(bj.w, bj.y));
                float uni = __fsub_rn(__fadd_rn(ai, aj), inter);
                float iou = (uni > 0.0f) ? __fdiv_rn(inter, uni) : 0.0f;
                if (iou > 0.5f) bits |= 1u << (jd - lo);
            }
        }
        s_mask[i * NW + w] = bits;
    }
    __syncthreads();

    // ---------- phase F: greedy scan (warp 0, register-batched) + emit top-100 ----------
    if (tid < 32) {
        unsigned int mysup = 0;                     // lane w owns rows [32w, 32w+32)
        const int nb = (m + 31) >> 5;
        for (int b = 0; b < nb; b++) {
            unsigned int cur = __shfl_sync(FULLM, mysup, b);
            const int base = b << 5;
            const int rows = min(32, m - base);
            unsigned int wreg[32];
            #pragma unroll
            for (int k2 = 0; k2 < 32; k2++)
                wreg[k2] = (k2 < rows) ? s_mask[(base + k2) * NW + b] : 0u;
            #pragma unroll
            for (int k2 = 0; k2 < 32; k2++) {
                if (k2 < rows && !((cur >> k2) & 1u)) {
                    cur |= wreg[k2];                                  // register chain
                    if (lane < NW) mysup |= s_mask[(base + k2) * NW + lane];
                }
            }
        }
        // ordered compaction of kept entries, first TOPK, pad with sentinels
        int cnt = 0;
        for (int bs = 0; bs < m; bs += 32) {
            int t = bs + lane;
            unsigned int supw = __shfl_sync(FULLM, mysup, t >> 5);
            bool kept = (t < m) && !((supw >> (t & 31)) & 1u);
            unsigned int bal = __ballot_sync(FULLM, kept);
            int pos = cnt + __popc(bal & ((1u << lane) - 1u));
            if (kept && pos < TOPK) g_selkey[cls * TOPK + pos] = skey[t];
            cnt += __popc(bal);
        }
        cnt = min(cnt, TOPK);
        for (int p = cnt + lane; p < TOPK; p += 32) g_selkey[cls * TOPK + p] = SENTK;
    }

    // ---------- publish + elect last block ----------
    __threadfence();
    __syncthreads();
    if (tid == 0) {
        unsigned int r = atomicAdd(&g_done, 1u);
        __threadfence();
        s_last = (r == NCLS - 1) ? 1 : 0;
    }
    __syncthreads();
    if (!s_last) return;

    // ---------- last block: merge-sort 2000 candidates, write top-100 ----------
    unsigned long long* sk2 = reinterpret_cast<unsigned long long*>(s_mask);
    for (int t = tid; t < SORT2; t += NTHR)
        sk2[t] = (t < NSEL) ? g_selkey[t] : SENTK;
    __syncthreads();
    for (int k = 2; k <= SORT2; k <<= 1) {
        for (int jj = k >> 1; jj > 0; jj >>= 1) {
            #pragma unroll
            for (int t = tid; t < SORT2; t += NTHR) {
                int ixj = t ^ jj;
                if (ixj > t) {
                    unsigned long long a = sk2[t];
                    unsigned long long b = sk2[ixj];
                    bool asc = ((t & k) == 0);
                    if ((a > b) == asc) { sk2[t] = b; sk2[ixj] = a; }
                }
            }
            __syncthreads();
        }
    }

    if (tid < TOPK) {
        unsigned long long keyv = sk2[tid];
        if (keyv != SENTK) {
            unsigned int j = (unsigned int)keyv;
            int c = (int)(j % NCLS);
            int b = (int)(j / NCLS);
            int i = c * NBOX + b;
            float4 bx = reinterpret_cast<const float4*>(boxes)[i];
            out[tid * 4 + 0] = fminf(fmaxf(bx.x, 0.0f), IMGW);
            out[tid * 4 + 1] = fminf(fmaxf(bx.y, 0.0f), IMGH);
            out[tid * 4 + 2] = fminf(fmaxf(bx.z, 0.0f), IMGW);
            out[tid * 4 + 3] = fminf(fmaxf(bx.w, 0.0f), IMGH);
            out[4 * TOPK + tid] = inv_ord((unsigned int)(keyv >> 32));
            out[5 * TOPK + tid] = (float)pred_cls[i];
            out[6 * TOPK + tid] = 1.0f;
        } else {
            out[tid * 4 + 0] = 0.0f;
            out[tid * 4 + 1] = 0.0f;
            out[tid * 4 + 2] = 0.0f;
            out[tid * 4 + 3] = 0.0f;
            out[4 * TOPK + tid] = 0.0f;
            out[5 * TOPK + tid] = -1.0f;
            out[6 * TOPK + tid] = 0.0f;
        }
    }
    if (tid == 0) {                 // reset for next replay (all blocks are done)
        g_maxBits = 0u;
        g_cnt1   = 0u;
        g_done   = 0u;
        __threadfence();
    }
}

// ---------------- launch ----------------
extern "C" void kernel_launch(void* const* d_in, const int* in_sizes, int n_in,
                              void* d_out, int out_size) {
    const int*   pred_cls = (const int*)d_in[0];
    const float* boxes    = (const float*)d_in[1];
    const float* scores   = (const float*)d_in[2];
    float* out = (float*)d_out;
    k_all<<<NCLS, NTHR>>>(boxes, scores, pred_cls, out);
}

// round 4
// speedup vs baseline: 4.7269x; 2.5913x over previous
#include <cuda_runtime.h>
#include <math_constants.h>

#define NN     8000
#define NCLS   20
#define NBOX   400
#define SORTN  512
#define IMGW   1333.0f
#define IMGH   800.0f
#define TOPK   100
#define NSEL   (NCLS * TOPK)     // 2000
#define SORT2  2048
#define NW     13                // 400 bits -> 13 u32 words
#define SENTK  0xFFFFFFFFFFFFFFFFull
#define FULLM  0xFFFFFFFFu

// ---------------- device scratch ----------------
__device__ unsigned long long g_skey[NCLS * SORTN];   // sorted keys per class
__device__ float4             g_sbox[NCLS * NBOX];    // clipped boxes in sorted order
__device__ int                g_m[NCLS];              // valid count per class
__device__ unsigned int       g_mask[NCLS * NBOX * NW];
__device__ unsigned long long g_selkey[NSEL];
__device__ unsigned int       g_maxBits = 0u;         // reset by k4 each replay

// descending-sortable mapping (ascending u64 sort -> descending float score)
__device__ __forceinline__ unsigned int ord_desc(float f) {
    unsigned int u = __float_as_uint(f);
    unsigned int m = (u & 0x80000000u) ? ~u : (u | 0x80000000u);
    return ~m;
}
__device__ __forceinline__ float inv_ord(unsigned int o) {
    unsigned int m = ~o;
    unsigned int u = (m & 0x80000000u) ? (m & 0x7FFFFFFFu) : ~m;
    return __uint_as_float(u);
}
__device__ __forceinline__ unsigned long long shfl_xor_u64(unsigned long long v, int jj) {
    unsigned int lo = (unsigned int)v, hi = (unsigned int)(v >> 32);
    lo = __shfl_xor_sync(FULLM, lo, jj);
    hi = __shfl_xor_sync(FULLM, hi, jj);
    return ((unsigned long long)hi << 32) | lo;
}
__device__ __forceinline__ unsigned long long uminll(unsigned long long a, unsigned long long b) { return a < b ? a : b; }
__device__ __forceinline__ unsigned long long umaxll(unsigned long long a, unsigned long long b) { return a > b ? a : b; }

// ---------------- k1: per-class load/clip/key + hybrid bitonic sort ----------------
__global__ void __launch_bounds__(SORTN) k1(const float* __restrict__ boxes,
                                            const float* __restrict__ scores) {
    __shared__ unsigned long long skey[SORTN];
    __shared__ float4       s_cbox[NBOX];
    __shared__ unsigned int s_wmax[16];

    const int cls = blockIdx.x, tid = threadIdx.x, lane = tid & 31;

    float lmax = 0.0f;
    bool  valid = false;
    unsigned long long v = SENTK;
    if (tid < NBOX) {
        float4 bx = reinterpret_cast<const float4*>(boxes)[cls * NBOX + tid];
        float2 sc = reinterpret_cast<const float2*>(scores)[cls * NBOX + tid];
        bool fin = isfinite(bx.x) && isfinite(bx.y) && isfinite(bx.z) && isfinite(bx.w)
                && isfinite(sc.x) && isfinite(sc.y);
        float x1 = fminf(fmaxf(bx.x, 0.0f), IMGW);
        float y1 = fminf(fmaxf(bx.y, 0.0f), IMGH);
        float x2 = fminf(fmaxf(bx.z, 0.0f), IMGW);
        float y2 = fminf(fmaxf(bx.w, 0.0f), IMGH);
        valid = fin && (sc.x > 0.05f);
        float masked = valid ? sc.x : -CUDART_INF_F;
        unsigned int j = (unsigned int)(tid * NCLS + cls);       // transposed index
        v = ((unsigned long long)ord_desc(masked) << 32) | j;
        s_cbox[tid] = make_float4(x1, y1, x2, y2);
        lmax = fmaxf(fmaxf(x1, x2), fmaxf(y1, y2));
    }
    unsigned int wb = __reduce_max_sync(FULLM, __float_as_uint(lmax));
    if (lane == 0) s_wmax[tid >> 5] = wb;
    const int m = __syncthreads_count(valid);
    if (tid == 0) {
        unsigned int mx = 0;
        #pragma unroll
        for (int w = 0; w < 16; w++) mx = max(mx, s_wmax[w]);
        atomicMax(&g_maxBits, mx);
    }

    // hybrid bitonic sort: smem stages for jj>=32, register/shfl stages for jj<=16
    for (int k = 2; k <= SORTN; k <<= 1) {
        for (int jj = k >> 1; jj >= 32; jj >>= 1) {
            skey[tid] = v;
            __syncthreads();
            unsigned long long p = skey[tid ^ jj];
            bool km = (((tid & k) == 0) == ((tid & jj) == 0));
            v = km ? uminll(v, p) : umaxll(v, p);
            __syncthreads();
        }
        int j0 = (k >> 1) < 16 ? (k >> 1) : 16;
        for (int jj = j0; jj >= 1; jj >>= 1) {
            unsigned long long p = shfl_xor_u64(v, jj);
            bool km = (((tid & k) == 0) == ((tid & jj) == 0));
            v = km ? uminll(v, p) : umaxll(v, p);
        }
    }

    g_skey[cls * SORTN + tid] = v;
    if (tid < m) {
        unsigned int j = (unsigned int)v;
        int b = (int)(j / NCLS);
        g_sbox[cls * NBOX + tid] = s_cbox[b];
    }
    if (tid == 0) g_m[cls] = m;
}

// ---------------- k2: mask matrix, 260 blocks (class x 32-row tile) ----------------
__global__ void __launch_bounds__(416) k2() {
    __shared__ float4 s_b[NBOX];
    __shared__ float  s_a[NBOX];

    const int c = blockIdx.y, ty = blockIdx.x;
    const int tid = threadIdx.x;
    const int wd = tid >> 5, lane = tid & 31;
    const int m = g_m[c];

    const float offv  = __fadd_rn(__uint_as_float(g_maxBits), 1.0f);
    const float shift = __fmul_rn((float)c, offv);

    for (int t = tid; t < m; t += 416) {
        float4 bx = g_sbox[c * NBOX + t];
        float4 sb = make_float4(__fadd_rn(bx.x, shift), __fadd_rn(bx.y, shift),
                                __fadd_rn(bx.z, shift), __fadd_rn(bx.w, shift));
        s_b[t] = sb;
        s_a[t] = __fmul_rn(__fsub_rn(sb.z, sb.x), __fsub_rn(sb.w, sb.y));
    }
    __syncthreads();

    const int i = ty * 32 + lane;
    if (i >= m) return;

    unsigned int bits = 0;
    const int lo = wd * 32;
    const int hi = min(m, lo + 32);
    const int st = max(lo, i + 1);
    if (st < hi) {
        float4 bi = s_b[i];
        float  ai = s_a[i];
        for (int jd = st; jd < hi; jd++) {
            float4 bj = s_b[jd];
            float iw = fmaxf(__fsub_rn(fminf(bi.z, bj.z), fmaxf(bi.x, bj.x)), 0.0f);
            float ih = fmaxf(__fsub_rn(fminf(bi.w, bj.w), fmaxf(bi.y, bj.y)), 0.0f);
            float inter = __fmul_rn(iw, ih);
            float uni = __fsub_rn(__fadd_rn(ai, s_a[jd]), inter);
            float iou = (uni > 0.0f) ? __fdiv_rn(inter, uni) : 0.0f;
            if (iou > 0.5f) bits |= 1u << (jd - lo);
        }
    }
    g_mask[(c * NBOX + i) * NW + wd] = bits;
}

// ---------------- k3: per-class greedy scan + emit top-100 kept ----------------
__global__ void __launch_bounds__(512) k3() {
    __shared__ unsigned int s_mask[NBOX * NW];

    const int c = blockIdx.x, tid = threadIdx.x, lane = tid & 31;
    const int m = g_m[c];

    for (int t = tid; t < m * NW; t += 512) s_mask[t] = g_mask[c * NBOX * NW + t];
    __syncthreads();
    if (tid >= 32) return;

    unsigned int mysup = 0;                       // lane w owns rows [32w, 32w+32)
    const int nb = (m + 31) >> 5;
    for (int b = 0; b < nb; b++) {
        unsigned int cur = __shfl_sync(FULLM, mysup, b);
        const int base = b << 5;
        const int rows = min(32, m - base);
        unsigned int wreg[32];
        #pragma unroll
        for (int q = 0; q < 32; q++)
            wreg[q] = (q < rows) ? s_mask[(base + q) * NW + b] : 0u;
        #pragma unroll
        for (int q = 0; q < 32; q++) {
            if (q < rows && !((cur >> q) & 1u)) {
                cur |= wreg[q];
                if (lane < NW) mysup |= s_mask[(base + q) * NW + lane];
            }
        }
    }
    int cnt = 0;
    for (int bs = 0; bs < m; bs += 32) {
        int t = bs + lane;
        unsigned int supw = __shfl_sync(FULLM, mysup, t >> 5);
        bool kept = (t < m) && !((supw >> (t & 31)) & 1u);
        unsigned int bal = __ballot_sync(FULLM, kept);
        int pos = cnt + __popc(bal & ((1u << lane) - 1u));
        if (kept && pos < TOPK) g_selkey[c * TOPK + pos] = g_skey[c * SORTN + t];
        cnt += __popc(bal);
    }
    cnt = min(cnt, TOPK);
    for (int p = cnt + lane; p < TOPK; p += 32) g_selkey[c * TOPK + p] = SENTK;
}

// ---------------- k4: hybrid bitonic on 2048 candidates + output ----------------
__global__ void __launch_bounds__(1024) k4(const float* __restrict__ boxes,
                                           const int* __restrict__ pred_cls,
                                           float* __restrict__ out) {
    __shared__ unsigned long long sk[SORT2];
    const int tid = threadIdx.x;

    unsigned long long v1 = (tid        < NSEL) ? g_selkey[tid]        : SENTK;
    unsigned long long v2 = (tid + 1024 < NSEL) ? g_selkey[tid + 1024] : SENTK;

    for (int k = 2; k <= SORT2; k <<= 1) {
        for (int jj = k >> 1; jj >= 32; jj >>= 1) {
            sk[tid] = v1;
            sk[tid + 1024] = v2;
            __syncthreads();
            unsigned long long p1 = sk[tid ^ jj];
            unsigned long long p2 = sk[(tid + 1024) ^ jj];
            {
                int t = tid;
                bool km = (((t & k) == 0) == ((t & jj) == 0));
                v1 = km ? uminll(v1, p1) : umaxll(v1, p1);
            }
            {
                int t = tid + 1024;
                bool km = (((t & k) == 0) == ((t & jj) == 0));
                v2 = km ? uminll(v2, p2) : umaxll(v2, p2);
            }
            __syncthreads();
        }
        int j0 = (k >> 1) < 16 ? (k >> 1) : 16;
        for (int jj = j0; jj >= 1; jj >>= 1) {
            unsigned long long p1 = shfl_xor_u64(v1, jj);
            unsigned long long p2 = shfl_xor_u64(v2, jj);
            {
                int t = tid;
                bool km = (((t & k) == 0) == ((t & jj) == 0));
                v1 = km ? uminll(v1, p1) : umaxll(v1, p1);
            }
            {
                int t = tid + 1024;
                bool km = (((t & k) == 0) == ((t & jj) == 0));
                v2 = km ? uminll(v2, p2) : umaxll(v2, p2);
            }
        }
    }

    if (tid < TOPK) {
        unsigned long long keyv = v1;             // sorted element index == tid
        if (keyv != SENTK) {
            unsigned int j = (unsigned int)keyv;
            int c = (int)(j % NCLS);
            int b = (int)(j / NCLS);
            int i = c * NBOX + b;
            float4 bx = reinterpret_cast<const float4*>(boxes)[i];
            out[tid * 4 + 0] = fminf(fmaxf(bx.x, 0.0f), IMGW);
            out[tid * 4 + 1] = fminf(fmaxf(bx.y, 0.0f), IMGH);
            out[tid * 4 + 2] = fminf(fmaxf(bx.z, 0.0f), IMGW);
            out[tid * 4 + 3] = fminf(fmaxf(bx.w, 0.0f), IMGH);
            out[4 * TOPK + tid] = inv_ord((unsigned int)(keyv >> 32));
            out[5 * TOPK + tid] = (float)pred_cls[i];
            out[6 * TOPK + tid] = 1.0f;
        } else {
            out[tid * 4 + 0] = 0.0f;
            out[tid * 4 + 1] = 0.0f;
            out[tid * 4 + 2] = 0.0f;
            out[tid * 4 + 3] = 0.0f;
            out[4 * TOPK + tid] = 0.0f;
            out[5 * TOPK + tid] = -1.0f;
            out[6 * TOPK + tid] = 0.0f;
        }
    }
    if (tid == 0) g_maxBits = 0u;                 // reset for next graph replay
}

// ---------------- launch ----------------
extern "C" void kernel_launch(void* const* d_in, const int* in_sizes, int n_in,
                              void* d_out, int out_size) {
    const int*   pred_cls = (const int*)d_in[0];
    const float* boxes    = (const float*)d_in[1];
    const float* scores   = (const float*)d_in[2];
    float* out = (float*)d_out;

    k1<<<NCLS, SORTN>>>(boxes, scores);
    k2<<<dim3(13, NCLS), 416>>>();
    k3<<<NCLS, 512>>>();
    k4<<<1, 1024>>>(boxes, pred_cls, out);
}

// round 5
// speedup vs baseline: 5.1631x; 1.0923x over previous
#include <cuda_runtime.h>
#include <math_constants.h>

#define NN     8000
#define NCLS   20
#define NBOX   400
#define SORTN  512
#define IMGW   1333.0f
#define IMGH   800.0f
#define TOPK   100
#define NSEL   (NCLS * TOPK)     // 2000
#define NW     13                // 400 bits -> 13 u32 words
#define SENTK  0xFFFFFFFFFFFFFFFFull
#define FULLM  0xFFFFFFFFu

// ---------------- device scratch ----------------
__device__ unsigned long long g_skey[NCLS * SORTN];   // sorted keys per class
__device__ float4             g_sbox[NCLS * NBOX];    // clipped boxes in sorted order
__device__ int                g_m[NCLS];              // valid count per class
__device__ unsigned int       g_mask[NCLS * NBOX * NW];
__device__ unsigned long long g_selkey[NSEL];         // per class: sorted kept top-100 (sentinel pad)
__device__ unsigned int       g_maxBits = 0u;         // reset by k4 each replay

// descending-sortable mapping (ascending u64 sort -> descending float score)
__device__ __forceinline__ unsigned int ord_desc(float f) {
    unsigned int u = __float_as_uint(f);
    unsigned int m = (u & 0x80000000u) ? ~u : (u | 0x80000000u);
    return ~m;
}
__device__ __forceinline__ float inv_ord(unsigned int o) {
    unsigned int m = ~o;
    unsigned int u = (m & 0x80000000u) ? (m & 0x7FFFFFFFu) : ~m;
    return __uint_as_float(u);
}
__device__ __forceinline__ unsigned long long shfl_xor_u64(unsigned long long v, int jj) {
    unsigned int lo = (unsigned int)v, hi = (unsigned int)(v >> 32);
    lo = __shfl_xor_sync(FULLM, lo, jj);
    hi = __shfl_xor_sync(FULLM, hi, jj);
    return ((unsigned long long)hi << 32) | lo;
}
__device__ __forceinline__ unsigned long long uminll(unsigned long long a, unsigned long long b) { return a < b ? a : b; }
__device__ __forceinline__ unsigned long long umaxll(unsigned long long a, unsigned long long b) { return a > b ? a : b; }

// ---------------- k1: per-class load/clip/key + hybrid bitonic sort ----------------
__global__ void __launch_bounds__(SORTN) k1(const float* __restrict__ boxes,
                                            const float* __restrict__ scores) {
    __shared__ unsigned long long skey[SORTN];
    __shared__ float4       s_cbox[NBOX];
    __shared__ unsigned int s_wmax[16];

    const int cls = blockIdx.x, tid = threadIdx.x, lane = tid & 31;

    float lmax = 0.0f;
    bool  valid = false;
    unsigned long long v = SENTK;
    if (tid < NBOX) {
        float4 bx = reinterpret_cast<const float4*>(boxes)[cls * NBOX + tid];
        float2 sc = reinterpret_cast<const float2*>(scores)[cls * NBOX + tid];
        bool fin = isfinite(bx.x) && isfinite(bx.y) && isfinite(bx.z) && isfinite(bx.w)
                && isfinite(sc.x) && isfinite(sc.y);
        float x1 = fminf(fmaxf(bx.x, 0.0f), IMGW);
        float y1 = fminf(fmaxf(bx.y, 0.0f), IMGH);
        float x2 = fminf(fmaxf(bx.z, 0.0f), IMGW);
        float y2 = fminf(fmaxf(bx.w, 0.0f), IMGH);
        valid = fin && (sc.x > 0.05f);
        float masked = valid ? sc.x : -CUDART_INF_F;
        unsigned int j = (unsigned int)(tid * NCLS + cls);       // transposed index
        v = ((unsigned long long)ord_desc(masked) << 32) | j;
        s_cbox[tid] = make_float4(x1, y1, x2, y2);
        lmax = fmaxf(fmaxf(x1, x2), fmaxf(y1, y2));
    }
    unsigned int wb = __reduce_max_sync(FULLM, __float_as_uint(lmax));
    if (lane == 0) s_wmax[tid >> 5] = wb;
    const int m = __syncthreads_count(valid);
    if (tid == 0) {
        unsigned int mx = 0;
        #pragma unroll
        for (int w = 0; w < 16; w++) mx = max(mx, s_wmax[w]);
        atomicMax(&g_maxBits, mx);
    }

    // hybrid bitonic sort: smem stages for jj>=32, register/shfl stages for jj<=16
    for (int k = 2; k <= SORTN; k <<= 1) {
        for (int jj = k >> 1; jj >= 32; jj >>= 1) {
            skey[tid] = v;
            __syncthreads();
            unsigned long long p = skey[tid ^ jj];
            bool km = (((tid & k) == 0) == ((tid & jj) == 0));
            v = km ? uminll(v, p) : umaxll(v, p);
            __syncthreads();
        }
        int j0 = (k >> 1) < 16 ? (k >> 1) : 16;
        for (int jj = j0; jj >= 1; jj >>= 1) {
            unsigned long long p = shfl_xor_u64(v, jj);
            bool km = (((tid & k) == 0) == ((tid & jj) == 0));
            v = km ? uminll(v, p) : umaxll(v, p);
        }
    }

    g_skey[cls * SORTN + tid] = v;
    if (tid < m) {
        unsigned int j = (unsigned int)v;
        int b = (int)(j / NCLS);
        g_sbox[cls * NBOX + tid] = s_cbox[b];
    }
    if (tid == 0) g_m[cls] = m;
}

// ---------------- k2: mask matrix, 260 blocks (class x 32-row tile) ----------------
__global__ void __launch_bounds__(416) k2() {
    __shared__ float4 s_b[NBOX];
    __shared__ float  s_a[NBOX];

    const int c = blockIdx.y, ty = blockIdx.x;
    const int tid = threadIdx.x;
    const int wd = tid >> 5, lane = tid & 31;
    const int m = g_m[c];

    const float offv  = __fadd_rn(__uint_as_float(g_maxBits), 1.0f);
    const float shift = __fmul_rn((float)c, offv);

    for (int t = tid; t < m; t += 416) {
        float4 bx = g_sbox[c * NBOX + t];
        float4 sb = make_float4(__fadd_rn(bx.x, shift), __fadd_rn(bx.y, shift),
                                __fadd_rn(bx.z, shift), __fadd_rn(bx.w, shift));
        s_b[t] = sb;
        s_a[t] = __fmul_rn(__fsub_rn(sb.z, sb.x), __fsub_rn(sb.w, sb.y));
    }
    __syncthreads();

    const int i = ty * 32 + lane;
    if (i >= m) return;

    unsigned int bits = 0;
    const int lo = wd * 32;
    const int hi = min(m, lo + 32);
    const int st = max(lo, i + 1);
    if (st < hi) {
        float4 bi = s_b[i];
        float  ai = s_a[i];
        for (int jd = st; jd < hi; jd++) {
            float4 bj = s_b[jd];
            float iw = fmaxf(__fsub_rn(fminf(bi.z, bj.z), fmaxf(bi.x, bj.x)), 0.0f);
            float ih = fmaxf(__fsub_rn(fminf(bi.w, bj.w), fmaxf(bi.y, bj.y)), 0.0f);
            float inter = __fmul_rn(iw, ih);
            float uni = __fsub_rn(__fadd_rn(ai, s_a[jd]), inter);
            float iou = (uni > 0.0f) ? __fdiv_rn(inter, uni) : 0.0f;
            if (iou > 0.5f) bits |= 1u << (jd - lo);
        }
    }
    g_mask[(c * NBOX + i) * NW + wd] = bits;
}

// ---------------- k3: per-class greedy scan + emit top-100 kept ----------------
__global__ void __launch_bounds__(512) k3() {
    __shared__ unsigned int s_mask[NBOX * NW];

    const int c = blockIdx.x, tid = threadIdx.x, lane = tid & 31;
    const int m = g_m[c];

    for (int t = tid; t < m * NW; t += 512) s_mask[t] = g_mask[c * NBOX * NW + t];
    __syncthreads();
    if (tid >= 32) return;

    unsigned int mysup = 0;                       // lane w owns rows [32w, 32w+32)
    const int nb = (m + 31) >> 5;
    for (int b = 0; b < nb; b++) {
        unsigned int cur = __shfl_sync(FULLM, mysup, b);
        const int base = b << 5;
        const int rows = min(32, m - base);
        unsigned int wreg[32];
        #pragma unroll
        for (int q = 0; q < 32; q++)
            wreg[q] = (q < rows) ? s_mask[(base + q) * NW + b] : 0u;
        #pragma unroll
        for (int q = 0; q < 32; q++) {
            if (q < rows && !((cur >> q) & 1u)) {
                cur |= wreg[q];
                if (lane < NW) mysup |= s_mask[(base + q) * NW + lane];
            }
        }
    }
    int cnt = 0;
    for (int bs = 0; bs < m; bs += 32) {
        int t = bs + lane;
        unsigned int supw = __shfl_sync(FULLM, mysup, t >> 5);
        bool kept = (t < m) && !((supw >> (t & 31)) & 1u);
        unsigned int bal = __ballot_sync(FULLM, kept);
        int pos = cnt + __popc(bal & ((1u << lane) - 1u));
        if (kept && pos < TOPK) g_selkey[c * TOPK + pos] = g_skey[c * SORTN + t];
        cnt += __popc(bal);
    }
    cnt = min(cnt, TOPK);
    for (int p = cnt + lane; p < TOPK; p += 32) g_selkey[c * TOPK + p] = SENTK;
}

// ---------------- k4: merge-by-rank of 20 sorted lists -> top-100 output ----------------
__global__ void __launch_bounds__(128) k4(const float* __restrict__ boxes,
                                          const int* __restrict__ pred_cls,
                                          float* __restrict__ out) {
    __shared__ unsigned long long sk[NSEL];       // 16 KB: all candidate keys
    __shared__ int s_wcnt[4];

    const int c = blockIdx.x, tid = threadIdx.x;

    for (int t = tid; t < NSEL; t += 128) sk[t] = g_selkey[t];
    __syncthreads();

    // block 0: write default rows [T, 100) (T = total valid candidates)
    if (c == 0) {
        int cnt = 0;
        for (int t = tid; t < NSEL; t += 128) cnt += (sk[t] != SENTK) ? 1 : 0;
        cnt = __reduce_add_sync(FULLM, cnt);
        if ((tid & 31) == 0) s_wcnt[tid >> 5] = cnt;
        __syncthreads();
        int T = s_wcnt[0] + s_wcnt[1] + s_wcnt[2] + s_wcnt[3];
        if (T < TOPK && tid < TOPK - T) {
            int r = T + tid;
            out[r * 4 + 0] = 0.0f;
            out[r * 4 + 1] = 0.0f;
            out[r * 4 + 2] = 0.0f;
            out[r * 4 + 3] = 0.0f;
            out[4 * TOPK + r] = 0.0f;
            out[5 * TOPK + r] = -1.0f;
            out[6 * TOPK + r] = 0.0f;
        }
        if (tid == 0) g_maxBits = 0u;             // reset for next graph replay
    }

    // rank this block's class elements against the other 19 sorted lists
    if (tid < TOPK) {
        unsigned long long e = sk[c * TOPK + tid];
        if (e != SENTK) {
            int rank = tid;                       // position within own sorted list
            #pragma unroll
            for (int c2 = 0; c2 < NCLS; c2++) {
                if (c2 == c) continue;
                const unsigned long long* seg = sk + c2 * TOPK;
                int lo = 0;                       // lower_bound: #elements < e
                #pragma unroll
                for (int s = 64; s > 0; s >>= 1) {
                    int p = lo + s;
                    if (p <= TOPK && seg[p - 1] < e) lo = p;
                }
                rank += lo;
            }
            if (rank < TOPK) {
                unsigned int j = (unsigned int)e;
                int cc = (int)(j % NCLS);
                int b  = (int)(j / NCLS);
                int i  = cc * NBOX + b;
                float4 bx = reinterpret_cast<const float4*>(boxes)[i];
                out[rank * 4 + 0] = fminf(fmaxf(bx.x, 0.0f), IMGW);
                out[rank * 4 + 1] = fminf(fmaxf(bx.y, 0.0f), IMGH);
                out[rank * 4 + 2] = fminf(fmaxf(bx.z, 0.0f), IMGW);
                out[rank * 4 + 3] = fminf(fmaxf(bx.w, 0.0f), IMGH);
                out[4 * TOPK + rank] = inv_ord((unsigned int)(e >> 32));
                out[5 * TOPK + rank] = (float)pred_cls[i];
                out[6 * TOPK + rank] = 1.0f;
            }
        }
    }
}

// ---------------- launch ----------------
extern "C" void kernel_launch(void* const* d_in, const int* in_sizes, int n_in,
                              void* d_out, int out_size) {
    const int*   pred_cls = (const int*)d_in[0];
    const float* boxes    = (const float*)d_in[1];
    const float* scores   = (const float*)d_in[2];
    float* out = (float*)d_out;

    k1<<<NCLS, SORTN>>>(boxes, scores);
    k2<<<dim3(13, NCLS), 416>>>();
    k3<<<NCLS, 512>>>();
    k4<<<NCLS, 128>>>(boxes, pred_cls, out);
}